// round 3
// baseline (speedup 1.0000x reference)
#include <cuda_runtime.h>
#include <cuda_bf16.h>
#include <cstdint>

#define B_  16
#define D_  128
#define HH  48
#define WW  48
#define N_  (HH*WW)      // 2304
#define NT  18           // N_/128

// log2(e)/TEMP  and ln(2)
#define KBT 20.60992915555662f
#define LN2 0.69314718055994531f

// ---------------- scratch (device globals; no runtime alloc) ----------------
__device__ __align__(256) float          g_T[B_*9];
__device__ __align__(256) __nv_bfloat16  g_fa[(size_t)B_*N_*D_];
__device__ __align__(256) __nv_bfloat16  g_wb[(size_t)B_*N_*D_];
__device__ __align__(256) float          g_mask[B_*N_];
__device__ double g_acc[2];

// ---------------- helpers ----------------
__device__ __forceinline__ void mul3(double* C, const double* A, const double* B) {
#pragma unroll
    for (int i = 0; i < 3; i++)
#pragma unroll
        for (int j = 0; j < 3; j++)
            C[i*3+j] = A[i*3+0]*B[0*3+j] + A[i*3+1]*B[1*3+j] + A[i*3+2]*B[2*3+j];
}

// fast 2^t on the FMA pipe: |t| <= ~22, rel err ~2.4e-6
__device__ __forceinline__ float exp2fast(float t) {
    float r = t + 12582912.0f;            // round-to-nearest via magic constant
    float f = t - (r - 12582912.0f);      // f in [-0.5, 0.5]
    int   j = __float_as_int(r);          // low bits hold rint(t) (biased, two's-comp ok)
    float p = 0.0013333558f;
    p = fmaf(p, f, 0.0096181291f);
    p = fmaf(p, f, 0.0555041086f);
    p = fmaf(p, f, 0.2402265070f);
    p = fmaf(p, f, 0.6931471806f);
    p = fmaf(p, f, 1.0f);
    return p * __int_as_float((j + 127) << 23);
}

// swizzled byte address inside a 128-row x 256B tile (16B chunks, conflict-free ldmatrix)
__device__ __forceinline__ unsigned sw_addr(unsigned base, int r, int c) {
    int cs = (c & 8) | ((c & 7) ^ (r & 7));
    return base + r * 256 + cs * 16;
}

__device__ __forceinline__ void ldsm4(unsigned addr, unsigned& r0, unsigned& r1,
                                      unsigned& r2, unsigned& r3) {
    asm volatile("ldmatrix.sync.aligned.m8n8.x4.shared.b16 {%0,%1,%2,%3}, [%4];"
                 : "=r"(r0), "=r"(r1), "=r"(r2), "=r"(r3) : "r"(addr));
}

__device__ __forceinline__ void mma16816(float c[4], unsigned a0, unsigned a1,
                                         unsigned a2, unsigned a3,
                                         unsigned b0, unsigned b1) {
    asm volatile(
        "mma.sync.aligned.m16n8k16.row.col.f32.bf16.bf16.f32 "
        "{%0,%1,%2,%3}, {%4,%5,%6,%7}, {%8,%9}, {%0,%1,%2,%3};"
        : "+f"(c[0]), "+f"(c[1]), "+f"(c[2]), "+f"(c[3])
        : "r"(a0), "r"(a1), "r"(a2), "r"(a3), "r"(b0), "r"(b1));
}

__device__ __forceinline__ void cpa16(unsigned saddr, const void* g) {
    asm volatile("cp.async.cg.shared.global [%0], [%1], 16;" :: "r"(saddr), "l"(g));
}

// ---------------- kernel 0: transform matrices + zero accumulators ----------------
__global__ void k_prep(const float* __restrict__ Ha, const float* __restrict__ Hb,
                       const float* __restrict__ M) {
    int b = threadIdx.x;
    if (b == 0) { g_acc[0] = 0.0; g_acc[1] = 0.0; }
    if (b >= B_) return;
    double A[9], Bm[9];
#pragma unroll
    for (int i = 0; i < 9; i++) { A[i] = Ha[b*9+i]; Bm[i] = Hb[b*9+i]; }
    // inverse of A (adjugate)
    double c00 = A[4]*A[8] - A[5]*A[7];
    double c01 = A[5]*A[6] - A[3]*A[8];
    double c02 = A[3]*A[7] - A[4]*A[6];
    double id  = 1.0 / (A[0]*c00 + A[1]*c01 + A[2]*c02);
    double Ai[9];
    Ai[0] = c00*id; Ai[1] = (A[2]*A[7]-A[1]*A[8])*id; Ai[2] = (A[1]*A[5]-A[2]*A[4])*id;
    Ai[3] = c01*id; Ai[4] = (A[0]*A[8]-A[2]*A[6])*id; Ai[5] = (A[2]*A[3]-A[0]*A[5])*id;
    Ai[6] = c02*id; Ai[7] = (A[1]*A[6]-A[0]*A[7])*id; Ai[8] = (A[0]*A[4]-A[1]*A[3])*id;
    double M3[9] = {M[0], M[1], M[2], M[3], M[4], M[5], 0.0, 0.0, 1.0};
    // X = Ai * S, S = diag(16,16,1)
    double X[9];
#pragma unroll
    for (int r = 0; r < 3; r++) {
        X[r*3+0] = Ai[r*3+0]*16.0; X[r*3+1] = Ai[r*3+1]*16.0; X[r*3+2] = Ai[r*3+2];
    }
    double Y[9], Z[9];
    mul3(Y, M3, X);
    mul3(Z, Bm, Y);
#pragma unroll
    for (int c = 0; c < 3; c++) { Z[0*3+c] *= (1.0/16.0); Z[1*3+c] *= (1.0/16.0); }
#pragma unroll
    for (int i = 0; i < 9; i++) g_T[b*9+i] = (float)Z[i];
}

// ---------------- kernel 1: normalize feats_a -> bf16 (B,N,D) ----------------
__global__ void k_fa(const float* __restrict__ fa) {
    __shared__ __nv_bfloat16 tile[D_ * 130];
    __shared__ float rn[128];
    const int b = blockIdx.y, p = threadIdx.x;
    const int n0 = blockIdx.x * 128;
    const float* src = fa + (size_t)b * D_ * N_ + n0 + p;
    float ss = 0.f;
#pragma unroll 4
    for (int d = 0; d < D_; d++) {
        float v = src[(size_t)d * N_];
        ss = fmaf(v, v, ss);
        tile[d*130 + p] = __float2bfloat16(v);
    }
    rn[p] = 1.f / fmaxf(sqrtf(ss), 1e-12f);
    __syncthreads();
    __nv_bfloat16* dst = g_fa + ((size_t)b * N_ + n0) * D_;
    const int t = threadIdx.x;
    for (int p2 = 0; p2 < 128; p2++) {
        float v = __bfloat162float(tile[t*130 + p2]) * rn[p2];
        dst[(size_t)p2 * D_ + t] = __float2bfloat16(v);
    }
}

// ---------------- kernel 2: warp + normalize feats_b -> bf16 (B,N,D), mask ----------------
__global__ void k_wb(const float* __restrict__ fb) {
    __shared__ __nv_bfloat16 tile[D_ * 130];
    __shared__ float rn[128];
    const int b = blockIdx.y, p = threadIdx.x;
    const int n0 = blockIdx.x * 128;
    const int n = n0 + p;
    const int x = n % WW, y = n / WW;
    const float* T = g_T + b * 9;
    float fx = (float)x, fy = (float)y;
    float u = T[0]*fx + T[1]*fy + T[2];
    float v = T[3]*fx + T[4]*fy + T[5];
    float z = T[6]*fx + T[7]*fy + T[8] + 1e-8f;
    float xn = 2.f * (u / z) / (float)(WW - 1) - 1.f;
    float yn = 2.f * (v / z) / (float)(HH - 1) - 1.f;
    float valid = (xn >= -1.f && xn <= 1.f && yn >= -1.f && yn <= 1.f) ? 1.f : 0.f;
    g_mask[b * N_ + n] = valid;
    float ix = (xn + 1.f) * 0.5f * (float)(WW - 1);
    float iy = (yn + 1.f) * 0.5f * (float)(HH - 1);
    float x0f = floorf(ix), y0f = floorf(iy);
    float wx1 = ix - x0f, wx0 = 1.f - wx1;
    float wy1 = iy - y0f, wy0 = 1.f - wy1;
    float xs[2] = {x0f, x0f + 1.f}, ys[2] = {y0f, y0f + 1.f};
    float wxv[2] = {wx0, wx1},      wyv[2] = {wy0, wy1};
    float w_[4]; int idx_[4];
#pragma unroll
    for (int cy = 0; cy < 2; cy++)
#pragma unroll
        for (int cx = 0; cx < 2; cx++) {
            float xf = xs[cx], yf = ys[cy];
            bool ok = (xf >= 0.f) && (xf <= (float)(WW-1)) && (yf >= 0.f) && (yf <= (float)(HH-1));
            int xi = min(max((int)xf, 0), WW - 1);
            int yi = min(max((int)yf, 0), HH - 1);
            idx_[cy*2+cx] = yi * WW + xi;
            w_[cy*2+cx] = ok ? (wxv[cx] * wyv[cy]) : 0.f;
        }
    const float* src = fb + (size_t)b * D_ * N_;
    float ss = 0.f;
#pragma unroll 4
    for (int d = 0; d < D_; d++) {
        const float* sd = src + (size_t)d * N_;
        float val = w_[0]*__ldg(sd+idx_[0]) + w_[1]*__ldg(sd+idx_[1])
                  + w_[2]*__ldg(sd+idx_[2]) + w_[3]*__ldg(sd+idx_[3]);
        ss = fmaf(val, val, ss);
        tile[d*130 + p] = __float2bfloat16(val);
    }
    rn[p] = 1.f / fmaxf(sqrtf(ss), 1e-12f);
    __syncthreads();
    __nv_bfloat16* dst = g_wb + ((size_t)b * N_ + n0) * D_;
    const int t = threadIdx.x;
    for (int p2 = 0; p2 < 128; p2++) {
        float vv = __bfloat162float(tile[t*130 + p2]) * rn[p2];
        dst[(size_t)p2 * D_ + t] = __float2bfloat16(vv);
    }
}

// ---------------- kernel 3: fused GEMM + exp2-sum + diag + masked reduce ----------------
extern __shared__ char smem_raw[];
__global__ void __launch_bounds__(256, 2) k_gemm() {
    const int b   = blockIdx.y;
    const int rt  = blockIdx.x;     // row tile (128 rows)
    const int tid = threadIdx.x;
    const int w   = tid >> 5, lane = tid & 31;
    const int g   = lane >> 2, tg = lane & 3;

    unsigned sm  = (unsigned)__cvta_generic_to_shared(smem_raw);
    unsigned sA  = sm;              // 32 KB
    unsigned sB0 = sm + 32768;      // 32 KB
    unsigned sB1 = sm + 65536;      // 32 KB
    float* sred  = (float*)(smem_raw + 98304);

    const __nv_bfloat16* Ag = g_fa + ((size_t)b * N_ + (size_t)rt * 128) * D_;
    const __nv_bfloat16* Bg = g_wb + (size_t)b * N_ * D_;

    // stage A (group), B0 (group), B1 (group)
#pragma unroll
    for (int j = 0; j < 8; j++) {
        int i = tid + j * 256, r = i >> 4, c = i & 15;
        cpa16(sw_addr(sA, r, c), (const char*)Ag + r * 256 + c * 16);
    }
    asm volatile("cp.async.commit_group;");
#pragma unroll
    for (int t0 = 0; t0 < 2; t0++) {
        unsigned sb = t0 ? sB1 : sB0;
        const char* src = (const char*)(Bg + (size_t)t0 * 128 * D_);
#pragma unroll
        for (int j = 0; j < 8; j++) {
            int i = tid + j * 256, r = i >> 4, c = i & 15;
            cpa16(sw_addr(sb, r, c), src + r * 256 + c * 16);
        }
        asm volatile("cp.async.commit_group;");
    }
    asm volatile("cp.async.wait_group 2;");   // A ready
    __syncthreads();

    // A fragments resident in registers for all 18 column tiles
    unsigned a[8][4];
    {
        int sel = lane >> 3;
        int rowoff = w * 16 + ((sel & 1) ? 8 : 0) + (lane & 7);
#pragma unroll
        for (int k = 0; k < 8; k++) {
            int c = 2 * k + ((sel & 2) ? 1 : 0);
            ldsm4(sw_addr(sA, rowoff, c), a[k][0], a[k][1], a[k][2], a[k][3]);
        }
    }

    float rs0 = 0.f, rs1 = 0.f, d0 = 0.f, d1 = 0.f;
    const int r0loc = w * 16 + g, r1loc = r0loc + 8;

    const int bsel   = lane >> 3;
    const int browof = ((bsel & 2) ? 8 : 0) + (lane & 7);
    const int bcsel  = (bsel & 1);

    for (int mt = 0; mt < NT; mt++) {
        if (mt < NT - 1) asm volatile("cp.async.wait_group 1;");
        else             asm volatile("cp.async.wait_group 0;");
        __syncthreads();
        unsigned sb = (mt & 1) ? sB1 : sB0;
        const bool diag = (mt == rt);

#pragma unroll 1
        for (int nn = 0; nn < 8; nn++) {
            float acc0[4] = {0.f, 0.f, 0.f, 0.f};
            float acc1[4] = {0.f, 0.f, 0.f, 0.f};
#pragma unroll
            for (int k = 0; k < 8; k++) {
                unsigned b0, b1, b2, b3;
                ldsm4(sw_addr(sb, nn * 16 + browof, 2 * k + bcsel), b0, b1, b2, b3);
                mma16816(acc0, a[k][0], a[k][1], a[k][2], a[k][3], b0, b1);
                mma16816(acc1, a[k][0], a[k][1], a[k][2], a[k][3], b2, b3);
            }
            float t00 = acc0[0] * KBT, t01 = acc0[1] * KBT;
            float t02 = acc0[2] * KBT, t03 = acc0[3] * KBT;
            float u00 = acc1[0] * KBT, u01 = acc1[1] * KBT;
            float u02 = acc1[2] * KBT, u03 = acc1[3] * KBT;
            rs0 += exp2fast(t00) + exp2fast(t01) + exp2fast(u00) + exp2fast(u01);
            rs1 += exp2fast(t02) + exp2fast(t03) + exp2fast(u02) + exp2fast(u03);
            if (diag) {
                int c0 = nn * 16 + 2 * tg;
                int c1 = c0 + 8;
                if (c0     == r0loc) d0 = t00;
                if (c0 + 1 == r0loc) d0 = t01;
                if (c0     == r1loc) d1 = t02;
                if (c0 + 1 == r1loc) d1 = t03;
                if (c1     == r0loc) d0 = u00;
                if (c1 + 1 == r0loc) d0 = u01;
                if (c1     == r1loc) d1 = u02;
                if (c1 + 1 == r1loc) d1 = u03;
            }
        }
        __syncthreads();
        if (mt + 2 < NT) {
            unsigned sbw = (mt & 1) ? sB1 : sB0;   // buffer just consumed
            const char* src = (const char*)(Bg + (size_t)(mt + 2) * 128 * D_);
#pragma unroll
            for (int j = 0; j < 8; j++) {
                int i = tid + j * 256, r = i >> 4, c = i & 15;
                cpa16(sw_addr(sbw, r, c), src + r * 256 + c * 16);
            }
            asm volatile("cp.async.commit_group;");
        }
    }

    // quad reduce (lanes 4g..4g+3 share rows); diag held by exactly one quad lane
    rs0 += __shfl_xor_sync(0xffffffffu, rs0, 1); rs0 += __shfl_xor_sync(0xffffffffu, rs0, 2);
    rs1 += __shfl_xor_sync(0xffffffffu, rs1, 1); rs1 += __shfl_xor_sync(0xffffffffu, rs1, 2);
    d0  += __shfl_xor_sync(0xffffffffu, d0, 1);  d0  += __shfl_xor_sync(0xffffffffu, d0, 2);
    d1  += __shfl_xor_sync(0xffffffffu, d1, 1);  d1  += __shfl_xor_sync(0xffffffffu, d1, 2);

    float lossv = 0.f, cntv = 0.f;
    if (tg == 0) {
        int gn0 = rt * 128 + r0loc;
        int gn1 = rt * 128 + r1loc;
        float m0 = g_mask[b * N_ + gn0];
        float m1 = g_mask[b * N_ + gn1];
        float l0 = LN2 * (log2f(rs0) - d0);
        float l1 = LN2 * (log2f(rs1) - d1);
        lossv = l0 * m0 + l1 * m1;
        cntv  = m0 + m1;
    }
#pragma unroll
    for (int off = 16; off; off >>= 1) {
        lossv += __shfl_xor_sync(0xffffffffu, lossv, off);
        cntv  += __shfl_xor_sync(0xffffffffu, cntv, off);
    }
    if (lane == 0) { sred[w] = lossv; sred[8 + w] = cntv; }
    __syncthreads();
    if (tid == 0) {
        float L = 0.f, C = 0.f;
#pragma unroll
        for (int i = 0; i < 8; i++) { L += sred[i]; C += sred[8 + i]; }
        atomicAdd(&g_acc[0], (double)L);
        atomicAdd(&g_acc[1], (double)C);
    }
}

// ---------------- kernel 4: finalize ----------------
__global__ void k_fin(float* out) {
    double t = g_acc[0], nv = g_acc[1];
    out[0] = (nv > 0.0) ? (float)(t / fmax(nv, 1.0)) : 0.f;
}

// ---------------- launch ----------------
extern "C" void kernel_launch(void* const* d_in, const int* in_sizes, int n_in,
                              void* d_out, int out_size) {
    (void)in_sizes; (void)n_in; (void)out_size;
    const float* fa = (const float*)d_in[0];
    const float* fb = (const float*)d_in[1];
    const float* Ha = (const float*)d_in[2];
    const float* Hb = (const float*)d_in[3];
    const float* M  = (const float*)d_in[4];
    float* out = (float*)d_out;

    cudaFuncSetAttribute(k_gemm, cudaFuncAttributeMaxDynamicSharedMemorySize, 98432);

    k_prep<<<1, 32>>>(Ha, Hb, M);
    dim3 gridN(NT, B_);
    k_fa<<<gridN, 128>>>(fa);
    k_wb<<<gridN, 128>>>(fb);
    k_gemm<<<dim3(NT, B_), 256, 98432>>>();
    k_fin<<<1, 1>>>(out);
}

// round 4
// speedup vs baseline: 1.1227x; 1.1227x over previous
#include <cuda_runtime.h>
#include <cuda_bf16.h>
#include <cstdint>

#define B_  16
#define D_  128
#define HH  48
#define WW  48
#define N_  (HH*WW)      // 2304
#define NT  18           // N_/128

// log2(e)/TEMP  and ln(2)
#define KBT 20.60992915555662f
#define LN2 0.69314718055994531f

// ---------------- scratch (device globals; no runtime alloc) ----------------
__device__ __align__(256) float          g_T[B_*9];
__device__ __align__(256) __nv_bfloat16  g_fa[(size_t)B_*N_*D_];
__device__ __align__(256) __nv_bfloat16  g_wb[(size_t)B_*N_*D_];
__device__ __align__(256) float          g_mask[B_*N_];
__device__ double g_acc[2];

// ---------------- helpers ----------------
__device__ __forceinline__ void mul3(double* C, const double* A, const double* B) {
#pragma unroll
    for (int i = 0; i < 3; i++)
#pragma unroll
        for (int j = 0; j < 3; j++)
            C[i*3+j] = A[i*3+0]*B[0*3+j] + A[i*3+1]*B[1*3+j] + A[i*3+2]*B[2*3+j];
}

// 2^x on the MUFU pipe (single instruction, ~2^-21 rel err, |x|<=21 here)
__device__ __forceinline__ float ex2(float x) {
    float y;
    asm("ex2.approx.f32 %0, %1;" : "=f"(y) : "f"(x));
    return y;
}

// swizzled byte address inside a 128-row x 256B tile (16B chunks, conflict-free ldmatrix)
__device__ __forceinline__ unsigned sw_addr(unsigned base, int r, int c) {
    int cs = (c & 8) | ((c & 7) ^ (r & 7));
    return base + r * 256 + cs * 16;
}

__device__ __forceinline__ void ldsm4(unsigned addr, unsigned& r0, unsigned& r1,
                                      unsigned& r2, unsigned& r3) {
    asm volatile("ldmatrix.sync.aligned.m8n8.x4.shared.b16 {%0,%1,%2,%3}, [%4];"
                 : "=r"(r0), "=r"(r1), "=r"(r2), "=r"(r3) : "r"(addr));
}

__device__ __forceinline__ void mma16816(float c[4], unsigned a0, unsigned a1,
                                         unsigned a2, unsigned a3,
                                         unsigned b0, unsigned b1) {
    asm volatile(
        "mma.sync.aligned.m16n8k16.row.col.f32.bf16.bf16.f32 "
        "{%0,%1,%2,%3}, {%4,%5,%6,%7}, {%8,%9}, {%0,%1,%2,%3};"
        : "+f"(c[0]), "+f"(c[1]), "+f"(c[2]), "+f"(c[3])
        : "r"(a0), "r"(a1), "r"(a2), "r"(a3), "r"(b0), "r"(b1));
}

__device__ __forceinline__ void cpa16(unsigned saddr, const void* g) {
    asm volatile("cp.async.cg.shared.global [%0], [%1], 16;" :: "r"(saddr), "l"(g));
}

// ---------------- kernel 0: transform matrices + zero accumulators ----------------
__global__ void k_prep(const float* __restrict__ Ha, const float* __restrict__ Hb,
                       const float* __restrict__ M) {
    int b = threadIdx.x;
    if (b == 0) { g_acc[0] = 0.0; g_acc[1] = 0.0; }
    if (b >= B_) return;
    double A[9], Bm[9];
#pragma unroll
    for (int i = 0; i < 9; i++) { A[i] = Ha[b*9+i]; Bm[i] = Hb[b*9+i]; }
    double c00 = A[4]*A[8] - A[5]*A[7];
    double c01 = A[5]*A[6] - A[3]*A[8];
    double c02 = A[3]*A[7] - A[4]*A[6];
    double id  = 1.0 / (A[0]*c00 + A[1]*c01 + A[2]*c02);
    double Ai[9];
    Ai[0] = c00*id; Ai[1] = (A[2]*A[7]-A[1]*A[8])*id; Ai[2] = (A[1]*A[5]-A[2]*A[4])*id;
    Ai[3] = c01*id; Ai[4] = (A[0]*A[8]-A[2]*A[6])*id; Ai[5] = (A[2]*A[3]-A[0]*A[5])*id;
    Ai[6] = c02*id; Ai[7] = (A[1]*A[6]-A[0]*A[7])*id; Ai[8] = (A[0]*A[4]-A[1]*A[3])*id;
    double M3[9] = {M[0], M[1], M[2], M[3], M[4], M[5], 0.0, 0.0, 1.0};
    double X[9];
#pragma unroll
    for (int r = 0; r < 3; r++) {
        X[r*3+0] = Ai[r*3+0]*16.0; X[r*3+1] = Ai[r*3+1]*16.0; X[r*3+2] = Ai[r*3+2];
    }
    double Y[9], Z[9];
    mul3(Y, M3, X);
    mul3(Z, Bm, Y);
#pragma unroll
    for (int c = 0; c < 3; c++) { Z[0*3+c] *= (1.0/16.0); Z[1*3+c] *= (1.0/16.0); }
#pragma unroll
    for (int i = 0; i < 9; i++) g_T[b*9+i] = (float)Z[i];
}

// ---------------- kernel 1: normalize (+ optional warp) -> bf16 (B,N,D) ----------------
// grid (NT, B_, 2): z=0 processes feats_a, z=1 warps+processes feats_b.
// 256 threads: (p = tid&127, dh = tid>>7) split the D loop in half.
__global__ void __launch_bounds__(256) k_pre(const float* __restrict__ fa,
                                             const float* __restrict__ fb) {
    __shared__ __nv_bfloat16 tile[D_ * 130];
    __shared__ float rn[128];
    __shared__ float ss2[256];
    const int b = blockIdx.y, tid = threadIdx.x;
    const int p = tid & 127, dh = tid >> 7;
    const int n0 = blockIdx.x * 128;
    const int n = n0 + p;

    float ss = 0.f;
    if (blockIdx.z == 0) {
        const float* src = fa + (size_t)b * D_ * N_ + n;
#pragma unroll 4
        for (int j = 0; j < 64; j++) {
            int d = dh * 64 + j;
            float v = __ldg(src + (size_t)d * N_);
            ss = fmaf(v, v, ss);
            tile[d*130 + p] = __float2bfloat16(v);
        }
    } else {
        const int x = n % WW, y = n / WW;
        const float* T = g_T + b * 9;
        float fx = (float)x, fy = (float)y;
        float u = T[0]*fx + T[1]*fy + T[2];
        float v = T[3]*fx + T[4]*fy + T[5];
        float z = T[6]*fx + T[7]*fy + T[8] + 1e-8f;
        float xn = 2.f * (u / z) / (float)(WW - 1) - 1.f;
        float yn = 2.f * (v / z) / (float)(HH - 1) - 1.f;
        float valid = (xn >= -1.f && xn <= 1.f && yn >= -1.f && yn <= 1.f) ? 1.f : 0.f;
        if (dh == 0) g_mask[b * N_ + n] = valid;
        float ix = (xn + 1.f) * 0.5f * (float)(WW - 1);
        float iy = (yn + 1.f) * 0.5f * (float)(HH - 1);
        float x0f = floorf(ix), y0f = floorf(iy);
        float wx1 = ix - x0f, wx0 = 1.f - wx1;
        float wy1 = iy - y0f, wy0 = 1.f - wy1;
        float xs[2] = {x0f, x0f + 1.f}, ys[2] = {y0f, y0f + 1.f};
        float wxv[2] = {wx0, wx1},      wyv[2] = {wy0, wy1};
        float w_[4]; int idx_[4];
#pragma unroll
        for (int cy = 0; cy < 2; cy++)
#pragma unroll
            for (int cx = 0; cx < 2; cx++) {
                float xf = xs[cx], yf = ys[cy];
                bool ok = (xf >= 0.f) && (xf <= (float)(WW-1)) && (yf >= 0.f) && (yf <= (float)(HH-1));
                int xi = min(max((int)xf, 0), WW - 1);
                int yi = min(max((int)yf, 0), HH - 1);
                idx_[cy*2+cx] = yi * WW + xi;
                w_[cy*2+cx] = ok ? (wxv[cx] * wyv[cy]) : 0.f;
            }
        const float* src = fb + (size_t)b * D_ * N_;
#pragma unroll 4
        for (int j = 0; j < 64; j++) {
            int d = dh * 64 + j;
            const float* sd = src + (size_t)d * N_;
            float val = w_[0]*__ldg(sd+idx_[0]) + w_[1]*__ldg(sd+idx_[1])
                      + w_[2]*__ldg(sd+idx_[2]) + w_[3]*__ldg(sd+idx_[3]);
            ss = fmaf(val, val, ss);
            tile[d*130 + p] = __float2bfloat16(val);
        }
    }
    ss2[tid] = ss;
    __syncthreads();
    if (tid < 128) rn[tid] = 1.f / fmaxf(sqrtf(ss2[tid] + ss2[128 + tid]), 1e-12f);
    __syncthreads();

    // transpose out: each warp handles one row per iteration, uint2 (4xbf16) stores
    __nv_bfloat16* dstb = (blockIdx.z == 0) ? g_fa : g_wb;
    __nv_bfloat16* dst = dstb + ((size_t)b * N_ + n0) * D_;
    const int q = tid & 31;            // uint2 index within row (32 per 128-elem row)
    const int wrow = tid >> 5;         // 8 warps -> 8 rows per iteration
#pragma unroll 2
    for (int it = 0; it < 16; it++) {
        int p2 = it * 8 + wrow;
        float r = rn[p2];
        __nv_bfloat16 vv[4];
#pragma unroll
        for (int i = 0; i < 4; i++)
            vv[i] = __float2bfloat16(__bfloat162float(tile[(4*q + i)*130 + p2]) * r);
        uint2 pk;
        pk.x = ((unsigned)__bfloat16_as_ushort(vv[1]) << 16) | __bfloat16_as_ushort(vv[0]);
        pk.y = ((unsigned)__bfloat16_as_ushort(vv[3]) << 16) | __bfloat16_as_ushort(vv[2]);
        *reinterpret_cast<uint2*>(dst + (size_t)p2 * D_ + 4*q) = pk;
    }
}

// ---------------- kernel 3: fused GEMM + exp2-sum + diag + masked reduce ----------------
extern __shared__ char smem_raw[];
__global__ void __launch_bounds__(256, 2) k_gemm() {
    const int b   = blockIdx.y;
    const int rt  = blockIdx.x;     // row tile (128 rows)
    const int tid = threadIdx.x;
    const int w   = tid >> 5, lane = tid & 31;
    const int g   = lane >> 2, tg = lane & 3;

    unsigned sm  = (unsigned)__cvta_generic_to_shared(smem_raw);
    unsigned sA  = sm;              // 32 KB
    unsigned sB0 = sm + 32768;      // 32 KB
    unsigned sB1 = sm + 65536;      // 32 KB
    float* sred  = (float*)(smem_raw + 98304);

    const __nv_bfloat16* Ag = g_fa + ((size_t)b * N_ + (size_t)rt * 128) * D_;
    const __nv_bfloat16* Bg = g_wb + (size_t)b * N_ * D_;

#pragma unroll
    for (int j = 0; j < 8; j++) {
        int i = tid + j * 256, r = i >> 4, c = i & 15;
        cpa16(sw_addr(sA, r, c), (const char*)Ag + r * 256 + c * 16);
    }
    asm volatile("cp.async.commit_group;");
#pragma unroll
    for (int t0 = 0; t0 < 2; t0++) {
        unsigned sb = t0 ? sB1 : sB0;
        const char* src = (const char*)(Bg + (size_t)t0 * 128 * D_);
#pragma unroll
        for (int j = 0; j < 8; j++) {
            int i = tid + j * 256, r = i >> 4, c = i & 15;
            cpa16(sw_addr(sb, r, c), src + r * 256 + c * 16);
        }
        asm volatile("cp.async.commit_group;");
    }
    asm volatile("cp.async.wait_group 2;");   // A ready
    __syncthreads();

    // A fragments resident in registers for all 18 column tiles
    unsigned a[8][4];
    {
        int sel = lane >> 3;
        int rowoff = w * 16 + ((sel & 1) ? 8 : 0) + (lane & 7);
#pragma unroll
        for (int k = 0; k < 8; k++) {
            int c = 2 * k + ((sel & 2) ? 1 : 0);
            ldsm4(sw_addr(sA, rowoff, c), a[k][0], a[k][1], a[k][2], a[k][3]);
        }
    }

    float rs0 = 0.f, rs1 = 0.f, d0 = 0.f, d1 = 0.f;
    const int r0loc = w * 16 + g, r1loc = r0loc + 8;

    const int bsel   = lane >> 3;
    const int browof = ((bsel & 2) ? 8 : 0) + (lane & 7);
    const int bcsel  = (bsel & 1);

    for (int mt = 0; mt < NT; mt++) {
        if (mt < NT - 1) asm volatile("cp.async.wait_group 1;");
        else             asm volatile("cp.async.wait_group 0;");
        __syncthreads();
        unsigned sb = (mt & 1) ? sB1 : sB0;
        const bool diag = (mt == rt);

#pragma unroll 1
        for (int nn = 0; nn < 8; nn++) {
            float acc0[4] = {0.f, 0.f, 0.f, 0.f};
            float acc1[4] = {0.f, 0.f, 0.f, 0.f};
#pragma unroll
            for (int k = 0; k < 8; k++) {
                unsigned b0, b1, b2, b3;
                ldsm4(sw_addr(sb, nn * 16 + browof, 2 * k + bcsel), b0, b1, b2, b3);
                mma16816(acc0, a[k][0], a[k][1], a[k][2], a[k][3], b0, b1);
                mma16816(acc1, a[k][0], a[k][1], a[k][2], a[k][3], b2, b3);
            }
            float t00 = acc0[0] * KBT, t01 = acc0[1] * KBT;
            float t02 = acc0[2] * KBT, t03 = acc0[3] * KBT;
            float u00 = acc1[0] * KBT, u01 = acc1[1] * KBT;
            float u02 = acc1[2] * KBT, u03 = acc1[3] * KBT;
            rs0 += (ex2(t00) + ex2(t01)) + (ex2(u00) + ex2(u01));
            rs1 += (ex2(t02) + ex2(t03)) + (ex2(u02) + ex2(u03));
            if (diag) {
                int c0 = nn * 16 + 2 * tg;
                int c1 = c0 + 8;
                if (c0     == r0loc) d0 = t00;
                if (c0 + 1 == r0loc) d0 = t01;
                if (c0     == r1loc) d1 = t02;
                if (c0 + 1 == r1loc) d1 = t03;
                if (c1     == r0loc) d0 = u00;
                if (c1 + 1 == r0loc) d0 = u01;
                if (c1     == r1loc) d1 = u02;
                if (c1 + 1 == r1loc) d1 = u03;
            }
        }
        __syncthreads();
        if (mt + 2 < NT) {
            unsigned sbw = (mt & 1) ? sB1 : sB0;   // buffer just consumed
            const char* src = (const char*)(Bg + (size_t)(mt + 2) * 128 * D_);
#pragma unroll
            for (int j = 0; j < 8; j++) {
                int i = tid + j * 256, r = i >> 4, c = i & 15;
                cpa16(sw_addr(sbw, r, c), src + r * 256 + c * 16);
            }
            asm volatile("cp.async.commit_group;");
        }
    }

    // quad reduce (lanes 4g..4g+3 share rows); diag held by exactly one quad lane
    rs0 += __shfl_xor_sync(0xffffffffu, rs0, 1); rs0 += __shfl_xor_sync(0xffffffffu, rs0, 2);
    rs1 += __shfl_xor_sync(0xffffffffu, rs1, 1); rs1 += __shfl_xor_sync(0xffffffffu, rs1, 2);
    d0  += __shfl_xor_sync(0xffffffffu, d0, 1);  d0  += __shfl_xor_sync(0xffffffffu, d0, 2);
    d1  += __shfl_xor_sync(0xffffffffu, d1, 1);  d1  += __shfl_xor_sync(0xffffffffu, d1, 2);

    float lossv = 0.f, cntv = 0.f;
    if (tg == 0) {
        int gn0 = rt * 128 + r0loc;
        int gn1 = rt * 128 + r1loc;
        float m0 = g_mask[b * N_ + gn0];
        float m1 = g_mask[b * N_ + gn1];
        float l0 = LN2 * (log2f(rs0) - d0);
        float l1 = LN2 * (log2f(rs1) - d1);
        lossv = l0 * m0 + l1 * m1;
        cntv  = m0 + m1;
    }
#pragma unroll
    for (int off = 16; off; off >>= 1) {
        lossv += __shfl_xor_sync(0xffffffffu, lossv, off);
        cntv  += __shfl_xor_sync(0xffffffffu, cntv, off);
    }
    if (lane == 0) { sred[w] = lossv; sred[8 + w] = cntv; }
    __syncthreads();
    if (tid == 0) {
        float L = 0.f, C = 0.f;
#pragma unroll
        for (int i = 0; i < 8; i++) { L += sred[i]; C += sred[8 + i]; }
        atomicAdd(&g_acc[0], (double)L);
        atomicAdd(&g_acc[1], (double)C);
    }
}

// ---------------- kernel 4: finalize ----------------
__global__ void k_fin(float* out) {
    double t = g_acc[0], nv = g_acc[1];
    out[0] = (nv > 0.0) ? (float)(t / fmax(nv, 1.0)) : 0.f;
}

// ---------------- launch ----------------
extern "C" void kernel_launch(void* const* d_in, const int* in_sizes, int n_in,
                              void* d_out, int out_size) {
    (void)in_sizes; (void)n_in; (void)out_size;
    const float* fa = (const float*)d_in[0];
    const float* fb = (const float*)d_in[1];
    const float* Ha = (const float*)d_in[2];
    const float* Hb = (const float*)d_in[3];
    const float* M  = (const float*)d_in[4];
    float* out = (float*)d_out;

    cudaFuncSetAttribute(k_gemm, cudaFuncAttributeMaxDynamicSharedMemorySize, 98432);

    k_prep<<<1, 32>>>(Ha, Hb, M);
    k_pre<<<dim3(NT, B_, 2), 256>>>(fa, fb);
    k_gemm<<<dim3(NT, B_), 256, 98432>>>();
    k_fin<<<1, 1>>>(out);
}

// round 5
// speedup vs baseline: 1.2972x; 1.1554x over previous
#include <cuda_runtime.h>
#include <cuda_bf16.h>
#include <cstdint>

#define B_  16
#define D_  128
#define HH  48
#define WW  48
#define N_  (HH*WW)      // 2304
#define NT  18           // N_/128

// log2(e)/TEMP  and ln(2)
#define KBT 20.60992915555662f
#define LN2 0.69314718055994531f

// ---------------- scratch (device globals; no runtime alloc) ----------------
__device__ __align__(256) __nv_bfloat16  g_fa[(size_t)B_*N_*D_];   // pre-scaled by KBT
__device__ __align__(256) __nv_bfloat16  g_wb[(size_t)B_*N_*D_];
__device__ __align__(256) float          g_mask[B_*N_];
__device__ double g_acc[2];

// ---------------- helpers ----------------
__device__ __forceinline__ void mul3(double* C, const double* A, const double* B) {
#pragma unroll
    for (int i = 0; i < 3; i++)
#pragma unroll
        for (int j = 0; j < 3; j++)
            C[i*3+j] = A[i*3+0]*B[0*3+j] + A[i*3+1]*B[1*3+j] + A[i*3+2]*B[2*3+j];
}

// 2^x on the MUFU pipe (single instruction, ~2^-21 rel err, |x|<=21 here)
__device__ __forceinline__ float ex2(float x) {
    float y;
    asm("ex2.approx.f32 %0, %1;" : "=f"(y) : "f"(x));
    return y;
}

// swizzled byte address inside a 128-row x 256B tile (16B chunks, conflict-free ldmatrix)
__device__ __forceinline__ unsigned sw_addr(unsigned base, int r, int c) {
    int cs = (c & 8) | ((c & 7) ^ (r & 7));
    return base + r * 256 + cs * 16;
}

__device__ __forceinline__ void ldsm4(unsigned addr, unsigned& r0, unsigned& r1,
                                      unsigned& r2, unsigned& r3) {
    asm volatile("ldmatrix.sync.aligned.m8n8.x4.shared.b16 {%0,%1,%2,%3}, [%4];"
                 : "=r"(r0), "=r"(r1), "=r"(r2), "=r"(r3) : "r"(addr));
}

__device__ __forceinline__ void mma16816(float c[4], unsigned a0, unsigned a1,
                                         unsigned a2, unsigned a3,
                                         unsigned b0, unsigned b1) {
    asm volatile(
        "mma.sync.aligned.m16n8k16.row.col.f32.bf16.bf16.f32 "
        "{%0,%1,%2,%3}, {%4,%5,%6,%7}, {%8,%9}, {%0,%1,%2,%3};"
        : "+f"(c[0]), "+f"(c[1]), "+f"(c[2]), "+f"(c[3])
        : "r"(a0), "r"(a1), "r"(a2), "r"(a3), "r"(b0), "r"(b1));
}

__device__ __forceinline__ void cpa16(unsigned saddr, const void* g) {
    asm volatile("cp.async.cg.shared.global [%0], [%1], 16;" :: "r"(saddr), "l"(g));
}

// bf16 (packed in a u32) -> float, exact
__device__ __forceinline__ float bflo(unsigned u) { return __uint_as_float(u << 16); }
__device__ __forceinline__ float bfhi(unsigned u) { return __uint_as_float(u & 0xffff0000u); }
__device__ __forceinline__ unsigned pk2(float lo, float hi) {
    return ((unsigned)__bfloat16_as_ushort(__float2bfloat16(hi)) << 16)
         |  (unsigned)__bfloat16_as_ushort(__float2bfloat16(lo));
}

// ---------------- kernel 1: normalize (+ optional warp) -> bf16 (B,N,D) ----------------
// grid (NT, B_, 2): z=0 processes feats_a (scaled by KBT), z=1 warps+processes feats_b.
// 256 threads: (p = tid&127, dh = tid>>7) split the D loop in half.
// smem tile layout: [p][d] stride 130 elems -> conflict-free STS in the load phase,
// contiguous (2x LDS.32) reads in the transpose/store phase.
__global__ void __launch_bounds__(256) k_pre(const float* __restrict__ fa,
                                             const float* __restrict__ fb,
                                             const float* __restrict__ Ha,
                                             const float* __restrict__ Hb,
                                             const float* __restrict__ M) {
    __shared__ __nv_bfloat16 tile[128 * 130];
    __shared__ float rn[128];
    __shared__ float ss2[256];
    const int b = blockIdx.y, tid = threadIdx.x;
    const int p = tid & 127, dh = tid >> 7;
    const int n0 = blockIdx.x * 128;
    const int n = n0 + p;

    if (blockIdx.x == 0 && blockIdx.y == 0 && blockIdx.z == 0 && tid == 0) {
        g_acc[0] = 0.0; g_acc[1] = 0.0;
    }

    float ss = 0.f;
    if (blockIdx.z == 0) {
        const float* src = fa + (size_t)b * D_ * N_ + n;
#pragma unroll 4
        for (int j = 0; j < 64; j++) {
            int d = dh * 64 + j;
            float v = __ldg(src + (size_t)d * N_);
            ss = fmaf(v, v, ss);
            tile[p*130 + d] = __float2bfloat16(v);
        }
    } else {
        // compute T per-thread (double; near-identity so well-conditioned)
        double A[9], Bm[9];
#pragma unroll
        for (int i = 0; i < 9; i++) { A[i] = Ha[b*9+i]; Bm[i] = Hb[b*9+i]; }
        double c00 = A[4]*A[8] - A[5]*A[7];
        double c01 = A[5]*A[6] - A[3]*A[8];
        double c02 = A[3]*A[7] - A[4]*A[6];
        double id  = 1.0 / (A[0]*c00 + A[1]*c01 + A[2]*c02);
        double Ai[9];
        Ai[0] = c00*id; Ai[1] = (A[2]*A[7]-A[1]*A[8])*id; Ai[2] = (A[1]*A[5]-A[2]*A[4])*id;
        Ai[3] = c01*id; Ai[4] = (A[0]*A[8]-A[2]*A[6])*id; Ai[5] = (A[2]*A[3]-A[0]*A[5])*id;
        Ai[6] = c02*id; Ai[7] = (A[1]*A[6]-A[0]*A[7])*id; Ai[8] = (A[0]*A[4]-A[1]*A[3])*id;
        double M3[9] = {M[0], M[1], M[2], M[3], M[4], M[5], 0.0, 0.0, 1.0};
        double X[9];
#pragma unroll
        for (int r = 0; r < 3; r++) {
            X[r*3+0] = Ai[r*3+0]*16.0; X[r*3+1] = Ai[r*3+1]*16.0; X[r*3+2] = Ai[r*3+2];
        }
        double Y[9], Z[9];
        mul3(Y, M3, X);
        mul3(Z, Bm, Y);
#pragma unroll
        for (int c = 0; c < 3; c++) { Z[0*3+c] *= (1.0/16.0); Z[1*3+c] *= (1.0/16.0); }
        float T[9];
#pragma unroll
        for (int i = 0; i < 9; i++) T[i] = (float)Z[i];

        const int x = n % WW, y = n / WW;
        float fx = (float)x, fy = (float)y;
        float u = T[0]*fx + T[1]*fy + T[2];
        float v = T[3]*fx + T[4]*fy + T[5];
        float z = T[6]*fx + T[7]*fy + T[8] + 1e-8f;
        float xn = 2.f * (u / z) / (float)(WW - 1) - 1.f;
        float yn = 2.f * (v / z) / (float)(HH - 1) - 1.f;
        float valid = (xn >= -1.f && xn <= 1.f && yn >= -1.f && yn <= 1.f) ? 1.f : 0.f;
        if (dh == 0) g_mask[b * N_ + n] = valid;
        float ix = (xn + 1.f) * 0.5f * (float)(WW - 1);
        float iy = (yn + 1.f) * 0.5f * (float)(HH - 1);
        float x0f = floorf(ix), y0f = floorf(iy);
        float wx1 = ix - x0f, wx0 = 1.f - wx1;
        float wy1 = iy - y0f, wy0 = 1.f - wy1;
        float xs[2] = {x0f, x0f + 1.f}, ys[2] = {y0f, y0f + 1.f};
        float wxv[2] = {wx0, wx1},      wyv[2] = {wy0, wy1};
        float w_[4]; int idx_[4];
#pragma unroll
        for (int cy = 0; cy < 2; cy++)
#pragma unroll
            for (int cx = 0; cx < 2; cx++) {
                float xf = xs[cx], yf = ys[cy];
                bool ok = (xf >= 0.f) && (xf <= (float)(WW-1)) && (yf >= 0.f) && (yf <= (float)(HH-1));
                int xi = min(max((int)xf, 0), WW - 1);
                int yi = min(max((int)yf, 0), HH - 1);
                idx_[cy*2+cx] = yi * WW + xi;
                w_[cy*2+cx] = ok ? (wxv[cx] * wyv[cy]) : 0.f;
            }
        const float* src = fb + (size_t)b * D_ * N_;
#pragma unroll 4
        for (int j = 0; j < 64; j++) {
            int d = dh * 64 + j;
            const float* sd = src + (size_t)d * N_;
            float val = w_[0]*__ldg(sd+idx_[0]) + w_[1]*__ldg(sd+idx_[1])
                      + w_[2]*__ldg(sd+idx_[2]) + w_[3]*__ldg(sd+idx_[3]);
            ss = fmaf(val, val, ss);
            tile[p*130 + d] = __float2bfloat16(val);
        }
    }
    ss2[tid] = ss;
    __syncthreads();
    if (tid < 128) {
        float scale = (blockIdx.z == 0) ? KBT : 1.f;
        rn[tid] = scale / fmaxf(sqrtf(ss2[tid] + ss2[128 + tid]), 1e-12f);
    }
    __syncthreads();

    // transpose out: warp handles 8 rows total; uint2 (4xbf16) stores
    __nv_bfloat16* dstb = (blockIdx.z == 0) ? g_fa : g_wb;
    __nv_bfloat16* dst = dstb + ((size_t)b * N_ + n0) * D_;
    const int q = tid & 31;            // quad index within row (32 per 128-elem row)
    const int wrow = tid >> 5;         // 8 warps -> 8 rows per iteration
    const unsigned* t32 = reinterpret_cast<const unsigned*>(tile);
#pragma unroll 2
    for (int it = 0; it < 16; it++) {
        int p2 = it * 8 + wrow;
        float r = rn[p2];
        unsigned u0 = t32[p2 * 65 + 2*q];
        unsigned u1 = t32[p2 * 65 + 2*q + 1];
        uint2 pkv;
        pkv.x = pk2(bflo(u0) * r, bfhi(u0) * r);
        pkv.y = pk2(bflo(u1) * r, bfhi(u1) * r);
        *reinterpret_cast<uint2*>(dst + (size_t)p2 * D_ + 4*q) = pkv;
    }
}

// ---------------- kernel 3: fused GEMM + exp2-sum + diag + masked reduce ----------------
extern __shared__ char smem_raw[];
__global__ void __launch_bounds__(256, 2) k_gemm() {
    const int b   = blockIdx.y;
    const int rt  = blockIdx.x;     // row tile (128 rows)
    const int tid = threadIdx.x;
    const int w   = tid >> 5, lane = tid & 31;
    const int g   = lane >> 2, tg = lane & 3;

    unsigned sm  = (unsigned)__cvta_generic_to_shared(smem_raw);
    unsigned sA  = sm;              // 32 KB
    unsigned sB0 = sm + 32768;      // 32 KB
    unsigned sB1 = sm + 65536;      // 32 KB
    float* sred  = (float*)(smem_raw + 98304);

    const __nv_bfloat16* Ag = g_fa + ((size_t)b * N_ + (size_t)rt * 128) * D_;
    const __nv_bfloat16* Bg = g_wb + (size_t)b * N_ * D_;

#pragma unroll
    for (int j = 0; j < 8; j++) {
        int i = tid + j * 256, r = i >> 4, c = i & 15;
        cpa16(sw_addr(sA, r, c), (const char*)Ag + r * 256 + c * 16);
    }
    asm volatile("cp.async.commit_group;");
#pragma unroll
    for (int t0 = 0; t0 < 2; t0++) {
        unsigned sb = t0 ? sB1 : sB0;
        const char* src = (const char*)(Bg + (size_t)t0 * 128 * D_);
#pragma unroll
        for (int j = 0; j < 8; j++) {
            int i = tid + j * 256, r = i >> 4, c = i & 15;
            cpa16(sw_addr(sb, r, c), src + r * 256 + c * 16);
        }
        asm volatile("cp.async.commit_group;");
    }
    asm volatile("cp.async.wait_group 2;");   // A ready
    __syncthreads();

    // A fragments resident in registers for all 18 column tiles
    unsigned a[8][4];
    {
        int sel = lane >> 3;
        int rowoff = w * 16 + ((sel & 1) ? 8 : 0) + (lane & 7);
#pragma unroll
        for (int k = 0; k < 8; k++) {
            int c = 2 * k + ((sel & 2) ? 1 : 0);
            ldsm4(sw_addr(sA, rowoff, c), a[k][0], a[k][1], a[k][2], a[k][3]);
        }
    }

    float rs0 = 0.f, rs1 = 0.f, d0 = 0.f, d1 = 0.f;
    const int r0loc = w * 16 + g, r1loc = r0loc + 8;

    const int bsel   = lane >> 3;
    const int browof = ((bsel & 2) ? 8 : 0) + (lane & 7);
    const int bcsel  = (bsel & 1);

    // epilogue for one 128x16 sub-tile (values already scaled: logits*log2e/TEMP)
    #define EPILOGUE(P0, P1, NN)                                               \
        do {                                                                   \
            rs0 += (ex2((P0)[0]) + ex2((P0)[1])) + (ex2((P1)[0]) + ex2((P1)[1]));\
            rs1 += (ex2((P0)[2]) + ex2((P0)[3])) + (ex2((P1)[2]) + ex2((P1)[3]));\
            if (diag) {                                                        \
                int c0 = (NN) * 16 + 2 * tg;                                   \
                int c1 = c0 + 8;                                               \
                if (c0     == r0loc) d0 = (P0)[0];                             \
                if (c0 + 1 == r0loc) d0 = (P0)[1];                             \
                if (c0     == r1loc) d1 = (P0)[2];                             \
                if (c0 + 1 == r1loc) d1 = (P0)[3];                             \
                if (c1     == r0loc) d0 = (P1)[0];                             \
                if (c1 + 1 == r0loc) d0 = (P1)[1];                             \
                if (c1     == r1loc) d1 = (P1)[2];                             \
                if (c1 + 1 == r1loc) d1 = (P1)[3];                             \
            }                                                                  \
        } while (0)

    for (int mt = 0; mt < NT; mt++) {
        if (mt < NT - 1) asm volatile("cp.async.wait_group 1;");
        else             asm volatile("cp.async.wait_group 0;");
        __syncthreads();
        unsigned sb = (mt & 1) ? sB1 : sB0;
        const bool diag = (mt == rt);

        float p0[4], p1[4];      // previous sub-tile accumulators (pipelined epilogue)
#pragma unroll
        for (int nn = 0; nn < 8; nn++) {
            // epilogue of previous sub-tile runs on MUFU/FMA while this
            // sub-tile's ldsm+mma occupy LSU/tensor pipes
            if (nn > 0) EPILOGUE(p0, p1, nn - 1);
            float acc0[4] = {0.f, 0.f, 0.f, 0.f};
            float acc1[4] = {0.f, 0.f, 0.f, 0.f};
#pragma unroll
            for (int k = 0; k < 8; k++) {
                unsigned b0, b1, b2, b3;
                ldsm4(sw_addr(sb, nn * 16 + browof, 2 * k + bcsel), b0, b1, b2, b3);
                mma16816(acc0, a[k][0], a[k][1], a[k][2], a[k][3], b0, b1);
                mma16816(acc1, a[k][0], a[k][1], a[k][2], a[k][3], b2, b3);
            }
#pragma unroll
            for (int i = 0; i < 4; i++) { p0[i] = acc0[i]; p1[i] = acc1[i]; }
        }
        __syncthreads();
        if (mt + 2 < NT) {
            unsigned sbw = (mt & 1) ? sB1 : sB0;   // buffer just consumed
            const char* src = (const char*)(Bg + (size_t)(mt + 2) * 128 * D_);
#pragma unroll
            for (int j = 0; j < 8; j++) {
                int i = tid + j * 256, r = i >> 4, c = i & 15;
                cpa16(sw_addr(sbw, r, c), src + r * 256 + c * 16);
            }
            asm volatile("cp.async.commit_group;");
        }
        // last sub-tile's epilogue overlaps the prefetch we just issued
        EPILOGUE(p0, p1, 7);
    }
    #undef EPILOGUE

    // quad reduce (lanes 4g..4g+3 share rows); diag held by exactly one quad lane
    rs0 += __shfl_xor_sync(0xffffffffu, rs0, 1); rs0 += __shfl_xor_sync(0xffffffffu, rs0, 2);
    rs1 += __shfl_xor_sync(0xffffffffu, rs1, 1); rs1 += __shfl_xor_sync(0xffffffffu, rs1, 2);
    d0  += __shfl_xor_sync(0xffffffffu, d0, 1);  d0  += __shfl_xor_sync(0xffffffffu, d0, 2);
    d1  += __shfl_xor_sync(0xffffffffu, d1, 1);  d1  += __shfl_xor_sync(0xffffffffu, d1, 2);

    float lossv = 0.f, cntv = 0.f;
    if (tg == 0) {
        int gn0 = rt * 128 + r0loc;
        int gn1 = rt * 128 + r1loc;
        float m0 = g_mask[b * N_ + gn0];
        float m1 = g_mask[b * N_ + gn1];
        float l0 = LN2 * (log2f(rs0) - d0);
        float l1 = LN2 * (log2f(rs1) - d1);
        lossv = l0 * m0 + l1 * m1;
        cntv  = m0 + m1;
    }
#pragma unroll
    for (int off = 16; off; off >>= 1) {
        lossv += __shfl_xor_sync(0xffffffffu, lossv, off);
        cntv  += __shfl_xor_sync(0xffffffffu, cntv, off);
    }
    if (lane == 0) { sred[w] = lossv; sred[8 + w] = cntv; }
    __syncthreads();
    if (tid == 0) {
        float L = 0.f, C = 0.f;
#pragma unroll
        for (int i = 0; i < 8; i++) { L += sred[i]; C += sred[8 + i]; }
        atomicAdd(&g_acc[0], (double)L);
        atomicAdd(&g_acc[1], (double)C);
    }
}

// ---------------- kernel 4: finalize ----------------
__global__ void k_fin(float* out) {
    double t = g_acc[0], nv = g_acc[1];
    out[0] = (nv > 0.0) ? (float)(t / fmax(nv, 1.0)) : 0.f;
}

// ---------------- launch ----------------
extern "C" void kernel_launch(void* const* d_in, const int* in_sizes, int n_in,
                              void* d_out, int out_size) {
    (void)in_sizes; (void)n_in; (void)out_size;
    const float* fa = (const float*)d_in[0];
    const float* fb = (const float*)d_in[1];
    const float* Ha = (const float*)d_in[2];
    const float* Hb = (const float*)d_in[3];
    const float* M  = (const float*)d_in[4];
    float* out = (float*)d_out;

    cudaFuncSetAttribute(k_gemm, cudaFuncAttributeMaxDynamicSharedMemorySize, 98432);

    k_pre<<<dim3(NT, B_, 2), 256>>>(fa, fb, Ha, Hb, M);
    k_gemm<<<dim3(NT, B_), 256, 98432>>>();
    k_fin<<<1, 1>>>(out);
}

// round 6
// speedup vs baseline: 1.2997x; 1.0019x over previous
#include <cuda_runtime.h>
#include <cuda_bf16.h>
#include <cstdint>

#define B_  16
#define D_  128
#define HH  48
#define WW  48
#define N_  (HH*WW)      // 2304
#define NT  18           // N_/128

// log2(e)/TEMP  and ln(2)
#define KBT 20.60992915555662f
#define LN2 0.69314718055994531f

// ---------------- scratch (device globals; no runtime alloc) ----------------
__device__ __align__(256) __nv_bfloat16  g_fa[(size_t)B_*N_*D_];   // pre-scaled by KBT
__device__ __align__(256) __nv_bfloat16  g_wb[(size_t)B_*N_*D_];
__device__ __align__(256) float          g_mask[B_*N_];
__device__ double g_acc[2];

// ---------------- helpers ----------------
__device__ __forceinline__ void mul3(double* C, const double* A, const double* B) {
#pragma unroll
    for (int i = 0; i < 3; i++)
#pragma unroll
        for (int j = 0; j < 3; j++)
            C[i*3+j] = A[i*3+0]*B[0*3+j] + A[i*3+1]*B[1*3+j] + A[i*3+2]*B[2*3+j];
}

// 2^x on the MUFU pipe (single instruction, ~2^-21 rel err, |x|<=21 here)
__device__ __forceinline__ float ex2(float x) {
    float y;
    asm("ex2.approx.f32 %0, %1;" : "=f"(y) : "f"(x));
    return y;
}

// swizzled byte address inside a 128-row x 256B tile (16B chunks, conflict-free ldmatrix)
__device__ __forceinline__ unsigned sw_addr(unsigned base, int r, int c) {
    int cs = (c & 8) | ((c & 7) ^ (r & 7));
    return base + r * 256 + cs * 16;
}

__device__ __forceinline__ void ldsm4(unsigned addr, unsigned& r0, unsigned& r1,
                                      unsigned& r2, unsigned& r3) {
    asm volatile("ldmatrix.sync.aligned.m8n8.x4.shared.b16 {%0,%1,%2,%3}, [%4];"
                 : "=r"(r0), "=r"(r1), "=r"(r2), "=r"(r3) : "r"(addr));
}

__device__ __forceinline__ void mma16816(float c[4], unsigned a0, unsigned a1,
                                         unsigned a2, unsigned a3,
                                         unsigned b0, unsigned b1) {
    asm volatile(
        "mma.sync.aligned.m16n8k16.row.col.f32.bf16.bf16.f32 "
        "{%0,%1,%2,%3}, {%4,%5,%6,%7}, {%8,%9}, {%0,%1,%2,%3};"
        : "+f"(c[0]), "+f"(c[1]), "+f"(c[2]), "+f"(c[3])
        : "r"(a0), "r"(a1), "r"(a2), "r"(a3), "r"(b0), "r"(b1));
}

__device__ __forceinline__ void cpa16(unsigned saddr, const void* g) {
    asm volatile("cp.async.cg.shared.global [%0], [%1], 16;" :: "r"(saddr), "l"(g));
}

// bf16 (packed in a u32) -> float, exact
__device__ __forceinline__ float bflo(unsigned u) { return __uint_as_float(u << 16); }
__device__ __forceinline__ float bfhi(unsigned u) { return __uint_as_float(u & 0xffff0000u); }
__device__ __forceinline__ unsigned pk2(float lo, float hi) {
    return ((unsigned)__bfloat16_as_ushort(__float2bfloat16(hi)) << 16)
         |  (unsigned)__bfloat16_as_ushort(__float2bfloat16(lo));
}

// ---------------- kernel 1: normalize (+ optional warp) -> bf16 (B,N,D) ----------------
// grid (NT, B_, 2): z=0 processes feats_a (scaled by KBT), z=1 warps+processes feats_b.
// 256 threads: (p = tid&127, dh = tid>>7) split the D loop in half.
// Load loops use explicit register staging (16 outstanding LDGs) so the LDG
// latency chain is MLP-hidden instead of serialized behind FMA/STS.
__global__ void __launch_bounds__(256) k_pre(const float* __restrict__ fa,
                                             const float* __restrict__ fb,
                                             const float* __restrict__ Ha,
                                             const float* __restrict__ Hb,
                                             const float* __restrict__ M) {
    __shared__ __nv_bfloat16 tile[128 * 130];
    __shared__ float rn[128];
    __shared__ float ss2[256];
    const int b = blockIdx.y, tid = threadIdx.x;
    const int p = tid & 127, dh = tid >> 7;
    const int n0 = blockIdx.x * 128;
    const int n = n0 + p;

    if (blockIdx.x == 0 && blockIdx.y == 0 && blockIdx.z == 0 && tid == 0) {
        g_acc[0] = 0.0; g_acc[1] = 0.0;
    }

    float ss = 0.f;
    if (blockIdx.z == 0) {
        const float* src = fa + (size_t)b * D_ * N_ + (size_t)dh * 64 * N_ + n;
#pragma unroll
        for (int jj = 0; jj < 64; jj += 16) {
            float v[16];
#pragma unroll
            for (int i = 0; i < 16; i++)
                v[i] = __ldg(src + (size_t)(jj + i) * N_);
#pragma unroll
            for (int i = 0; i < 16; i++) {
                ss = fmaf(v[i], v[i], ss);
                tile[p*130 + dh*64 + jj + i] = __float2bfloat16(v[i]);
            }
        }
    } else {
        // compute T per-thread (double; near-identity so well-conditioned)
        double A[9], Bm[9];
#pragma unroll
        for (int i = 0; i < 9; i++) { A[i] = Ha[b*9+i]; Bm[i] = Hb[b*9+i]; }
        double c00 = A[4]*A[8] - A[5]*A[7];
        double c01 = A[5]*A[6] - A[3]*A[8];
        double c02 = A[3]*A[7] - A[4]*A[6];
        double id  = 1.0 / (A[0]*c00 + A[1]*c01 + A[2]*c02);
        double Ai[9];
        Ai[0] = c00*id; Ai[1] = (A[2]*A[7]-A[1]*A[8])*id; Ai[2] = (A[1]*A[5]-A[2]*A[4])*id;
        Ai[3] = c01*id; Ai[4] = (A[0]*A[8]-A[2]*A[6])*id; Ai[5] = (A[2]*A[3]-A[0]*A[5])*id;
        Ai[6] = c02*id; Ai[7] = (A[1]*A[6]-A[0]*A[7])*id; Ai[8] = (A[0]*A[4]-A[1]*A[3])*id;
        double M3[9] = {M[0], M[1], M[2], M[3], M[4], M[5], 0.0, 0.0, 1.0};
        double X[9];
#pragma unroll
        for (int r = 0; r < 3; r++) {
            X[r*3+0] = Ai[r*3+0]*16.0; X[r*3+1] = Ai[r*3+1]*16.0; X[r*3+2] = Ai[r*3+2];
        }
        double Y[9], Z[9];
        mul3(Y, M3, X);
        mul3(Z, Bm, Y);
#pragma unroll
        for (int c = 0; c < 3; c++) { Z[0*3+c] *= (1.0/16.0); Z[1*3+c] *= (1.0/16.0); }
        float T[9];
#pragma unroll
        for (int i = 0; i < 9; i++) T[i] = (float)Z[i];

        const int x = n % WW, y = n / WW;
        float fx = (float)x, fy = (float)y;
        float u = T[0]*fx + T[1]*fy + T[2];
        float v = T[3]*fx + T[4]*fy + T[5];
        float z = T[6]*fx + T[7]*fy + T[8] + 1e-8f;
        float xn = 2.f * (u / z) / (float)(WW - 1) - 1.f;
        float yn = 2.f * (v / z) / (float)(HH - 1) - 1.f;
        float valid = (xn >= -1.f && xn <= 1.f && yn >= -1.f && yn <= 1.f) ? 1.f : 0.f;
        if (dh == 0) g_mask[b * N_ + n] = valid;
        float ix = (xn + 1.f) * 0.5f * (float)(WW - 1);
        float iy = (yn + 1.f) * 0.5f * (float)(HH - 1);
        float x0f = floorf(ix), y0f = floorf(iy);
        float wx1 = ix - x0f, wx0 = 1.f - wx1;
        float wy1 = iy - y0f, wy0 = 1.f - wy1;
        float xs[2] = {x0f, x0f + 1.f}, ys[2] = {y0f, y0f + 1.f};
        float wxv[2] = {wx0, wx1},      wyv[2] = {wy0, wy1};
        float w_[4]; int idx_[4];
#pragma unroll
        for (int cy = 0; cy < 2; cy++)
#pragma unroll
            for (int cx = 0; cx < 2; cx++) {
                float xf = xs[cx], yf = ys[cy];
                bool ok = (xf >= 0.f) && (xf <= (float)(WW-1)) && (yf >= 0.f) && (yf <= (float)(HH-1));
                int xi = min(max((int)xf, 0), WW - 1);
                int yi = min(max((int)yf, 0), HH - 1);
                idx_[cy*2+cx] = yi * WW + xi;
                w_[cy*2+cx] = ok ? (wxv[cx] * wyv[cy]) : 0.f;
            }
        const float* src = fb + (size_t)b * D_ * N_ + (size_t)dh * 64 * N_;
#pragma unroll 2
        for (int jj = 0; jj < 64; jj += 4) {
            float v4[4][4];
#pragma unroll
            for (int i = 0; i < 4; i++) {
                const float* sd = src + (size_t)(jj + i) * N_;
                v4[i][0] = __ldg(sd + idx_[0]);
                v4[i][1] = __ldg(sd + idx_[1]);
                v4[i][2] = __ldg(sd + idx_[2]);
                v4[i][3] = __ldg(sd + idx_[3]);
            }
#pragma unroll
            for (int i = 0; i < 4; i++) {
                float val = w_[0]*v4[i][0] + w_[1]*v4[i][1]
                          + w_[2]*v4[i][2] + w_[3]*v4[i][3];
                ss = fmaf(val, val, ss);
                tile[p*130 + dh*64 + jj + i] = __float2bfloat16(val);
            }
        }
    }
    ss2[tid] = ss;
    __syncthreads();
    if (tid < 128) {
        float scale = (blockIdx.z == 0) ? KBT : 1.f;
        rn[tid] = scale / fmaxf(sqrtf(ss2[tid] + ss2[128 + tid]), 1e-12f);
    }
    __syncthreads();

    // transpose out: warp handles 8 rows total; uint2 (4xbf16) stores
    __nv_bfloat16* dstb = (blockIdx.z == 0) ? g_fa : g_wb;
    __nv_bfloat16* dst = dstb + ((size_t)b * N_ + n0) * D_;
    const int q = tid & 31;            // quad index within row (32 per 128-elem row)
    const int wrow = tid >> 5;         // 8 warps -> 8 rows per iteration
    const unsigned* t32 = reinterpret_cast<const unsigned*>(tile);
#pragma unroll 2
    for (int it = 0; it < 16; it++) {
        int p2 = it * 8 + wrow;
        float r = rn[p2];
        unsigned u0 = t32[p2 * 65 + 2*q];
        unsigned u1 = t32[p2 * 65 + 2*q + 1];
        uint2 pkv;
        pkv.x = pk2(bflo(u0) * r, bfhi(u0) * r);
        pkv.y = pk2(bflo(u1) * r, bfhi(u1) * r);
        *reinterpret_cast<uint2*>(dst + (size_t)p2 * D_ + 4*q) = pkv;
    }
}

// ---------------- kernel 3: fused GEMM + exp2-sum + diag + masked reduce ----------------
extern __shared__ char smem_raw[];
__global__ void __launch_bounds__(256, 2) k_gemm() {
    const int b   = blockIdx.y;
    const int rt  = blockIdx.x;     // row tile (128 rows)
    const int tid = threadIdx.x;
    const int w   = tid >> 5, lane = tid & 31;
    const int g   = lane >> 2, tg = lane & 3;

    unsigned sm  = (unsigned)__cvta_generic_to_shared(smem_raw);
    unsigned sA  = sm;              // 32 KB
    unsigned sB0 = sm + 32768;      // 32 KB
    unsigned sB1 = sm + 65536;      // 32 KB
    float* sred  = (float*)(smem_raw + 98304);

    const __nv_bfloat16* Ag = g_fa + ((size_t)b * N_ + (size_t)rt * 128) * D_;
    const __nv_bfloat16* Bg = g_wb + (size_t)b * N_ * D_;

#pragma unroll
    for (int j = 0; j < 8; j++) {
        int i = tid + j * 256, r = i >> 4, c = i & 15;
        cpa16(sw_addr(sA, r, c), (const char*)Ag + r * 256 + c * 16);
    }
    asm volatile("cp.async.commit_group;");
#pragma unroll
    for (int t0 = 0; t0 < 2; t0++) {
        unsigned sb = t0 ? sB1 : sB0;
        const char* src = (const char*)(Bg + (size_t)t0 * 128 * D_);
#pragma unroll
        for (int j = 0; j < 8; j++) {
            int i = tid + j * 256, r = i >> 4, c = i & 15;
            cpa16(sw_addr(sb, r, c), src + r * 256 + c * 16);
        }
        asm volatile("cp.async.commit_group;");
    }
    asm volatile("cp.async.wait_group 2;");   // A ready
    __syncthreads();

    // A fragments resident in registers for all 18 column tiles
    unsigned a[8][4];
    {
        int sel = lane >> 3;
        int rowoff = w * 16 + ((sel & 1) ? 8 : 0) + (lane & 7);
#pragma unroll
        for (int k = 0; k < 8; k++) {
            int c = 2 * k + ((sel & 2) ? 1 : 0);
            ldsm4(sw_addr(sA, rowoff, c), a[k][0], a[k][1], a[k][2], a[k][3]);
        }
    }

    float rs0 = 0.f, rs1 = 0.f, d0 = 0.f, d1 = 0.f;
    const int r0loc = w * 16 + g, r1loc = r0loc + 8;

    const int bsel   = lane >> 3;
    const int browof = ((bsel & 2) ? 8 : 0) + (lane & 7);
    const int bcsel  = (bsel & 1);

    // epilogue for one 128x16 sub-tile (values already scaled: logits*log2e/TEMP)
    #define EPILOGUE(P0, P1, NN)                                               \
        do {                                                                   \
            rs0 += (ex2((P0)[0]) + ex2((P0)[1])) + (ex2((P1)[0]) + ex2((P1)[1]));\
            rs1 += (ex2((P0)[2]) + ex2((P0)[3])) + (ex2((P1)[2]) + ex2((P1)[3]));\
            if (diag) {                                                        \
                int c0 = (NN) * 16 + 2 * tg;                                   \
                int c1 = c0 + 8;                                               \
                if (c0     == r0loc) d0 = (P0)[0];                             \
                if (c0 + 1 == r0loc) d0 = (P0)[1];                             \
                if (c0     == r1loc) d1 = (P0)[2];                             \
                if (c0 + 1 == r1loc) d1 = (P0)[3];                             \
                if (c1     == r0loc) d0 = (P1)[0];                             \
                if (c1 + 1 == r0loc) d0 = (P1)[1];                             \
                if (c1     == r1loc) d1 = (P1)[2];                             \
                if (c1 + 1 == r1loc) d1 = (P1)[3];                             \
            }                                                                  \
        } while (0)

    for (int mt = 0; mt < NT; mt++) {
        if (mt < NT - 1) asm volatile("cp.async.wait_group 1;");
        else             asm volatile("cp.async.wait_group 0;");
        __syncthreads();
        unsigned sb = (mt & 1) ? sB1 : sB0;
        const bool diag = (mt == rt);

        float p0[4], p1[4];      // previous sub-tile accumulators (pipelined epilogue)
#pragma unroll
        for (int nn = 0; nn < 8; nn++) {
            // epilogue of previous sub-tile runs on MUFU/FMA while this
            // sub-tile's ldsm+mma occupy LSU/tensor pipes
            if (nn > 0) EPILOGUE(p0, p1, nn - 1);
            float acc0[4] = {0.f, 0.f, 0.f, 0.f};
            float acc1[4] = {0.f, 0.f, 0.f, 0.f};
#pragma unroll
            for (int k = 0; k < 8; k++) {
                unsigned b0, b1, b2, b3;
                ldsm4(sw_addr(sb, nn * 16 + browof, 2 * k + bcsel), b0, b1, b2, b3);
                mma16816(acc0, a[k][0], a[k][1], a[k][2], a[k][3], b0, b1);
                mma16816(acc1, a[k][0], a[k][1], a[k][2], a[k][3], b2, b3);
            }
#pragma unroll
            for (int i = 0; i < 4; i++) { p0[i] = acc0[i]; p1[i] = acc1[i]; }
        }
        __syncthreads();
        if (mt + 2 < NT) {
            unsigned sbw = (mt & 1) ? sB1 : sB0;   // buffer just consumed
            const char* src = (const char*)(Bg + (size_t)(mt + 2) * 128 * D_);
#pragma unroll
            for (int j = 0; j < 8; j++) {
                int i = tid + j * 256, r = i >> 4, c = i & 15;
                cpa16(sw_addr(sbw, r, c), src + r * 256 + c * 16);
            }
            asm volatile("cp.async.commit_group;");
        }
        // last sub-tile's epilogue overlaps the prefetch we just issued
        EPILOGUE(p0, p1, 7);
    }
    #undef EPILOGUE

    // quad reduce (lanes 4g..4g+3 share rows); diag held by exactly one quad lane
    rs0 += __shfl_xor_sync(0xffffffffu, rs0, 1); rs0 += __shfl_xor_sync(0xffffffffu, rs0, 2);
    rs1 += __shfl_xor_sync(0xffffffffu, rs1, 1); rs1 += __shfl_xor_sync(0xffffffffu, rs1, 2);
    d0  += __shfl_xor_sync(0xffffffffu, d0, 1);  d0  += __shfl_xor_sync(0xffffffffu, d0, 2);
    d1  += __shfl_xor_sync(0xffffffffu, d1, 1);  d1  += __shfl_xor_sync(0xffffffffu, d1, 2);

    float lossv = 0.f, cntv = 0.f;
    if (tg == 0) {
        int gn0 = rt * 128 + r0loc;
        int gn1 = rt * 128 + r1loc;
        float m0 = g_mask[b * N_ + gn0];
        float m1 = g_mask[b * N_ + gn1];
        float l0 = LN2 * (log2f(rs0) - d0);
        float l1 = LN2 * (log2f(rs1) - d1);
        lossv = l0 * m0 + l1 * m1;
        cntv  = m0 + m1;
    }
#pragma unroll
    for (int off = 16; off; off >>= 1) {
        lossv += __shfl_xor_sync(0xffffffffu, lossv, off);
        cntv  += __shfl_xor_sync(0xffffffffu, cntv, off);
    }
    if (lane == 0) { sred[w] = lossv; sred[8 + w] = cntv; }
    __syncthreads();
    if (tid == 0) {
        float L = 0.f, C = 0.f;
#pragma unroll
        for (int i = 0; i < 8; i++) { L += sred[i]; C += sred[8 + i]; }
        atomicAdd(&g_acc[0], (double)L);
        atomicAdd(&g_acc[1], (double)C);
    }
}

// ---------------- kernel 4: finalize ----------------
__global__ void k_fin(float* out) {
    double t = g_acc[0], nv = g_acc[1];
    out[0] = (nv > 0.0) ? (float)(t / fmax(nv, 1.0)) : 0.f;
}

// ---------------- launch ----------------
extern "C" void kernel_launch(void* const* d_in, const int* in_sizes, int n_in,
                              void* d_out, int out_size) {
    (void)in_sizes; (void)n_in; (void)out_size;
    const float* fa = (const float*)d_in[0];
    const float* fb = (const float*)d_in[1];
    const float* Ha = (const float*)d_in[2];
    const float* Hb = (const float*)d_in[3];
    const float* M  = (const float*)d_in[4];
    float* out = (float*)d_out;

    cudaFuncSetAttribute(k_gemm, cudaFuncAttributeMaxDynamicSharedMemorySize, 98432);

    k_pre<<<dim3(NT, B_, 2), 256>>>(fa, fb, Ha, Hb, M);
    k_gemm<<<dim3(NT, B_), 256, 98432>>>();
    k_fin<<<1, 1>>>(out);
}

// round 7
// speedup vs baseline: 1.5611x; 1.2011x over previous
#include <cuda_runtime.h>
#include <cuda_bf16.h>
#include <cstdint>

#define B_  16
#define D_  128
#define HH  48
#define WW  48
#define N_  (HH*WW)      // 2304
#define NT  18           // N_/128 (gemm row tiles)
#define NP  36           // N_/64  (pre blocks per batch)

// log2(e)/TEMP  and ln(2)
#define KBT 20.60992915555662f
#define LN2 0.69314718055994531f

// ---------------- scratch (device globals; no runtime alloc) ----------------
__device__ __align__(256) __nv_bfloat16  g_fa[(size_t)B_*N_*D_];   // pre-scaled by KBT
__device__ __align__(256) __nv_bfloat16  g_wb[(size_t)B_*N_*D_];
__device__ __align__(256) float          g_mask[B_*N_];
__device__ double g_acc[2];

// ---------------- helpers ----------------
__device__ __forceinline__ void mul3f(float* C, const float* A, const float* B) {
#pragma unroll
    for (int i = 0; i < 3; i++)
#pragma unroll
        for (int j = 0; j < 3; j++)
            C[i*3+j] = A[i*3+0]*B[0*3+j] + A[i*3+1]*B[1*3+j] + A[i*3+2]*B[2*3+j];
}

// 2^x on the MUFU pipe (single instruction, ~2^-21 rel err, |x|<=21 here)
__device__ __forceinline__ float ex2(float x) {
    float y;
    asm("ex2.approx.f32 %0, %1;" : "=f"(y) : "f"(x));
    return y;
}

// swizzled byte address inside a 128-row x 256B tile (16B chunks, conflict-free ldmatrix)
__device__ __forceinline__ unsigned sw_addr(unsigned base, int r, int c) {
    int cs = (c & 8) | ((c & 7) ^ (r & 7));
    return base + r * 256 + cs * 16;
}

__device__ __forceinline__ void ldsm4(unsigned addr, unsigned& r0, unsigned& r1,
                                      unsigned& r2, unsigned& r3) {
    asm volatile("ldmatrix.sync.aligned.m8n8.x4.shared.b16 {%0,%1,%2,%3}, [%4];"
                 : "=r"(r0), "=r"(r1), "=r"(r2), "=r"(r3) : "r"(addr));
}

__device__ __forceinline__ void mma16816(float c[4], unsigned a0, unsigned a1,
                                         unsigned a2, unsigned a3,
                                         unsigned b0, unsigned b1) {
    asm volatile(
        "mma.sync.aligned.m16n8k16.row.col.f32.bf16.bf16.f32 "
        "{%0,%1,%2,%3}, {%4,%5,%6,%7}, {%8,%9}, {%0,%1,%2,%3};"
        : "+f"(c[0]), "+f"(c[1]), "+f"(c[2]), "+f"(c[3])
        : "r"(a0), "r"(a1), "r"(a2), "r"(a3), "r"(b0), "r"(b1));
}

__device__ __forceinline__ void cpa16(unsigned saddr, const void* g) {
    asm volatile("cp.async.cg.shared.global [%0], [%1], 16;" :: "r"(saddr), "l"(g));
}

// bf16 (packed in a u32) -> float, exact
__device__ __forceinline__ float bflo(unsigned u) { return __uint_as_float(u << 16); }
__device__ __forceinline__ float bfhi(unsigned u) { return __uint_as_float(u & 0xffff0000u); }
__device__ __forceinline__ unsigned pk2(float lo, float hi) {
    return ((unsigned)__bfloat16_as_ushort(__float2bfloat16(hi)) << 16)
         |  (unsigned)__bfloat16_as_ushort(__float2bfloat16(lo));
}

// ---------------- kernel 1: normalize (+ optional warp) -> bf16 (B,N,D) ----------------
// grid (NP, B_, 2): z=0 processes feats_a (scaled by KBT), z=1 warps+processes feats_b.
// 256 threads: p = tid&63 (pixel), dh = tid>>6 (0..3) -> 32 d-values per thread.
// 64-pixel tiles keep smem ~17KB and per-thread load chains short -> high residency.
__global__ void __launch_bounds__(256) k_pre(const float* __restrict__ fa,
                                             const float* __restrict__ fb,
                                             const float* __restrict__ Ha,
                                             const float* __restrict__ Hb,
                                             const float* __restrict__ M) {
    __shared__ __nv_bfloat16 tile[64 * 130];
    __shared__ float rn[64];
    __shared__ float ss2[256];
    const int b = blockIdx.y, tid = threadIdx.x;
    const int p = tid & 63, dh = tid >> 6;
    const int n0 = blockIdx.x * 64;
    const int n = n0 + p;

    if (blockIdx.x == 0 && blockIdx.y == 0 && blockIdx.z == 0 && tid == 0) {
        g_acc[0] = 0.0; g_acc[1] = 0.0;
    }

    float ss = 0.f;
    if (blockIdx.z == 0) {
        const float* src = fa + (size_t)b * D_ * N_ + (size_t)dh * 32 * N_ + n;
#pragma unroll
        for (int jj = 0; jj < 32; jj += 16) {
            float v[16];
#pragma unroll
            for (int i = 0; i < 16; i++)
                v[i] = __ldg(src + (size_t)(jj + i) * N_);
#pragma unroll
            for (int i = 0; i < 16; i++) {
                ss = fmaf(v[i], v[i], ss);
                tile[p*130 + dh*32 + jj + i] = __float2bfloat16(v[i]);
            }
        }
    } else {
        // T in fp32 (matches the fp32 reference; near-identity -> well-conditioned)
        float A[9], Bm[9];
#pragma unroll
        for (int i = 0; i < 9; i++) { A[i] = Ha[b*9+i]; Bm[i] = Hb[b*9+i]; }
        float c00 = A[4]*A[8] - A[5]*A[7];
        float c01 = A[5]*A[6] - A[3]*A[8];
        float c02 = A[3]*A[7] - A[4]*A[6];
        float id  = 1.0f / (A[0]*c00 + A[1]*c01 + A[2]*c02);
        float Ai[9];
        Ai[0] = c00*id; Ai[1] = (A[2]*A[7]-A[1]*A[8])*id; Ai[2] = (A[1]*A[5]-A[2]*A[4])*id;
        Ai[3] = c01*id; Ai[4] = (A[0]*A[8]-A[2]*A[6])*id; Ai[5] = (A[2]*A[3]-A[0]*A[5])*id;
        Ai[6] = c02*id; Ai[7] = (A[1]*A[6]-A[0]*A[7])*id; Ai[8] = (A[0]*A[4]-A[1]*A[3])*id;
        float M3[9] = {M[0], M[1], M[2], M[3], M[4], M[5], 0.f, 0.f, 1.f};
        float X[9];
#pragma unroll
        for (int r = 0; r < 3; r++) {
            X[r*3+0] = Ai[r*3+0]*16.f; X[r*3+1] = Ai[r*3+1]*16.f; X[r*3+2] = Ai[r*3+2];
        }
        float Y[9], T[9];
        mul3f(Y, M3, X);
        mul3f(T, Bm, Y);
#pragma unroll
        for (int c = 0; c < 3; c++) { T[0*3+c] *= (1.f/16.f); T[1*3+c] *= (1.f/16.f); }

        const int x = n % WW, y = n / WW;
        float fx = (float)x, fy = (float)y;
        float u = T[0]*fx + T[1]*fy + T[2];
        float v = T[3]*fx + T[4]*fy + T[5];
        float z = T[6]*fx + T[7]*fy + T[8] + 1e-8f;
        float xn = 2.f * (u / z) / (float)(WW - 1) - 1.f;
        float yn = 2.f * (v / z) / (float)(HH - 1) - 1.f;
        float valid = (xn >= -1.f && xn <= 1.f && yn >= -1.f && yn <= 1.f) ? 1.f : 0.f;
        if (dh == 0) g_mask[b * N_ + n] = valid;
        float ix = (xn + 1.f) * 0.5f * (float)(WW - 1);
        float iy = (yn + 1.f) * 0.5f * (float)(HH - 1);
        float x0f = floorf(ix), y0f = floorf(iy);
        float wx1 = ix - x0f, wx0 = 1.f - wx1;
        float wy1 = iy - y0f, wy0 = 1.f - wy1;
        float xs[2] = {x0f, x0f + 1.f}, ys[2] = {y0f, y0f + 1.f};
        float wxv[2] = {wx0, wx1},      wyv[2] = {wy0, wy1};
        float w_[4]; int idx_[4];
#pragma unroll
        for (int cy = 0; cy < 2; cy++)
#pragma unroll
            for (int cx = 0; cx < 2; cx++) {
                float xf = xs[cx], yf = ys[cy];
                bool ok = (xf >= 0.f) && (xf <= (float)(WW-1)) && (yf >= 0.f) && (yf <= (float)(HH-1));
                int xi = min(max((int)xf, 0), WW - 1);
                int yi = min(max((int)yf, 0), HH - 1);
                idx_[cy*2+cx] = yi * WW + xi;
                w_[cy*2+cx] = ok ? (wxv[cx] * wyv[cy]) : 0.f;
            }
        const float* src = fb + (size_t)b * D_ * N_ + (size_t)dh * 32 * N_;
#pragma unroll 2
        for (int jj = 0; jj < 32; jj += 4) {
            float v4[4][4];
#pragma unroll
            for (int i = 0; i < 4; i++) {
                const float* sd = src + (size_t)(jj + i) * N_;
                v4[i][0] = __ldg(sd + idx_[0]);
                v4[i][1] = __ldg(sd + idx_[1]);
                v4[i][2] = __ldg(sd + idx_[2]);
                v4[i][3] = __ldg(sd + idx_[3]);
            }
#pragma unroll
            for (int i = 0; i < 4; i++) {
                float val = w_[0]*v4[i][0] + w_[1]*v4[i][1]
                          + w_[2]*v4[i][2] + w_[3]*v4[i][3];
                ss = fmaf(val, val, ss);
                tile[p*130 + dh*32 + jj + i] = __float2bfloat16(val);
            }
        }
    }
    ss2[tid] = ss;
    __syncthreads();
    if (tid < 64) {
        float scale = (blockIdx.z == 0) ? KBT : 1.f;
        float s = ss2[tid] + ss2[64 + tid] + ss2[128 + tid] + ss2[192 + tid];
        rn[tid] = scale / fmaxf(sqrtf(s), 1e-12f);
    }
    __syncthreads();

    // transpose out: 8 warps x 8 iterations covers 64 rows; uint2 (4xbf16) stores
    __nv_bfloat16* dstb = (blockIdx.z == 0) ? g_fa : g_wb;
    __nv_bfloat16* dst = dstb + ((size_t)b * N_ + n0) * D_;
    const int q = tid & 31;            // u32-pair index within row (32 per 128-elem row)
    const int wrow = tid >> 5;         // 8 warps -> 8 rows per iteration
    const unsigned* t32 = reinterpret_cast<const unsigned*>(tile);
#pragma unroll 2
    for (int it = 0; it < 8; it++) {
        int p2 = it * 8 + wrow;
        float r = rn[p2];
        unsigned u0 = t32[p2 * 65 + 2*q];
        unsigned u1 = t32[p2 * 65 + 2*q + 1];
        uint2 pkv;
        pkv.x = pk2(bflo(u0) * r, bfhi(u0) * r);
        pkv.y = pk2(bflo(u1) * r, bfhi(u1) * r);
        *reinterpret_cast<uint2*>(dst + (size_t)p2 * D_ + 4*q) = pkv;
    }
}

// ---------------- kernel 3: fused GEMM + exp2-sum + diag + masked reduce ----------------
extern __shared__ char smem_raw[];
__global__ void __launch_bounds__(256, 2) k_gemm() {
    const int b   = blockIdx.y;
    const int rt  = blockIdx.x;     // row tile (128 rows)
    const int tid = threadIdx.x;
    const int w   = tid >> 5, lane = tid & 31;
    const int g   = lane >> 2, tg = lane & 3;

    unsigned sm  = (unsigned)__cvta_generic_to_shared(smem_raw);
    unsigned sA  = sm;              // 32 KB
    unsigned sB0 = sm + 32768;      // 32 KB
    unsigned sB1 = sm + 65536;      // 32 KB
    float* sred  = (float*)(smem_raw + 98304);

    const __nv_bfloat16* Ag = g_fa + ((size_t)b * N_ + (size_t)rt * 128) * D_;
    const __nv_bfloat16* Bg = g_wb + (size_t)b * N_ * D_;

#pragma unroll
    for (int j = 0; j < 8; j++) {
        int i = tid + j * 256, r = i >> 4, c = i & 15;
        cpa16(sw_addr(sA, r, c), (const char*)Ag + r * 256 + c * 16);
    }
    asm volatile("cp.async.commit_group;");
#pragma unroll
    for (int t0 = 0; t0 < 2; t0++) {
        unsigned sb = t0 ? sB1 : sB0;
        const char* src = (const char*)(Bg + (size_t)t0 * 128 * D_);
#pragma unroll
        for (int j = 0; j < 8; j++) {
            int i = tid + j * 256, r = i >> 4, c = i & 15;
            cpa16(sw_addr(sb, r, c), src + r * 256 + c * 16);
        }
        asm volatile("cp.async.commit_group;");
    }
    asm volatile("cp.async.wait_group 2;");   // A ready
    __syncthreads();

    // A fragments resident in registers for all 18 column tiles
    unsigned a[8][4];
    {
        int sel = lane >> 3;
        int rowoff = w * 16 + ((sel & 1) ? 8 : 0) + (lane & 7);
#pragma unroll
        for (int k = 0; k < 8; k++) {
            int c = 2 * k + ((sel & 2) ? 1 : 0);
            ldsm4(sw_addr(sA, rowoff, c), a[k][0], a[k][1], a[k][2], a[k][3]);
        }
    }

    float rs0 = 0.f, rs1 = 0.f, d0 = 0.f, d1 = 0.f;
    const int r0loc = w * 16 + g, r1loc = r0loc + 8;

    const int bsel   = lane >> 3;
    const int browof = ((bsel & 2) ? 8 : 0) + (lane & 7);
    const int bcsel  = (bsel & 1);

    // epilogue for one 128x16 sub-tile (values already scaled: logits*log2e/TEMP)
    #define EPILOGUE(P0, P1, NN)                                               \
        do {                                                                   \
            rs0 += (ex2((P0)[0]) + ex2((P0)[1])) + (ex2((P1)[0]) + ex2((P1)[1]));\
            rs1 += (ex2((P0)[2]) + ex2((P0)[3])) + (ex2((P1)[2]) + ex2((P1)[3]));\
            if (diag) {                                                        \
                int c0 = (NN) * 16 + 2 * tg;                                   \
                int c1 = c0 + 8;                                               \
                if (c0     == r0loc) d0 = (P0)[0];                             \
                if (c0 + 1 == r0loc) d0 = (P0)[1];                             \
                if (c0     == r1loc) d1 = (P0)[2];                             \
                if (c0 + 1 == r1loc) d1 = (P0)[3];                             \
                if (c1     == r0loc) d0 = (P1)[0];                             \
                if (c1 + 1 == r0loc) d0 = (P1)[1];                             \
                if (c1     == r1loc) d1 = (P1)[2];                             \
                if (c1 + 1 == r1loc) d1 = (P1)[3];                             \
            }                                                                  \
        } while (0)

    for (int mt = 0; mt < NT; mt++) {
        if (mt < NT - 1) asm volatile("cp.async.wait_group 1;");
        else             asm volatile("cp.async.wait_group 0;");
        __syncthreads();
        unsigned sb = (mt & 1) ? sB1 : sB0;
        const bool diag = (mt == rt);

        float p0[4], p1[4];      // previous sub-tile accumulators (pipelined epilogue)
#pragma unroll
        for (int nn = 0; nn < 8; nn++) {
            // epilogue of previous sub-tile runs on MUFU/FMA while this
            // sub-tile's ldsm+mma occupy LSU/tensor pipes
            if (nn > 0) EPILOGUE(p0, p1, nn - 1);
            float acc0[4] = {0.f, 0.f, 0.f, 0.f};
            float acc1[4] = {0.f, 0.f, 0.f, 0.f};
#pragma unroll
            for (int k = 0; k < 8; k++) {
                unsigned b0, b1, b2, b3;
                ldsm4(sw_addr(sb, nn * 16 + browof, 2 * k + bcsel), b0, b1, b2, b3);
                mma16816(acc0, a[k][0], a[k][1], a[k][2], a[k][3], b0, b1);
                mma16816(acc1, a[k][0], a[k][1], a[k][2], a[k][3], b2, b3);
            }
#pragma unroll
            for (int i = 0; i < 4; i++) { p0[i] = acc0[i]; p1[i] = acc1[i]; }
        }
        __syncthreads();
        if (mt + 2 < NT) {
            unsigned sbw = (mt & 1) ? sB1 : sB0;   // buffer just consumed
            const char* src = (const char*)(Bg + (size_t)(mt + 2) * 128 * D_);
#pragma unroll
            for (int j = 0; j < 8; j++) {
                int i = tid + j * 256, r = i >> 4, c = i & 15;
                cpa16(sw_addr(sbw, r, c), src + r * 256 + c * 16);
            }
            asm volatile("cp.async.commit_group;");
        }
        // last sub-tile's epilogue overlaps the prefetch we just issued
        EPILOGUE(p0, p1, 7);
    }
    #undef EPILOGUE

    // quad reduce (lanes 4g..4g+3 share rows); diag held by exactly one quad lane
    rs0 += __shfl_xor_sync(0xffffffffu, rs0, 1); rs0 += __shfl_xor_sync(0xffffffffu, rs0, 2);
    rs1 += __shfl_xor_sync(0xffffffffu, rs1, 1); rs1 += __shfl_xor_sync(0xffffffffu, rs1, 2);
    d0  += __shfl_xor_sync(0xffffffffu, d0, 1);  d0  += __shfl_xor_sync(0xffffffffu, d0, 2);
    d1  += __shfl_xor_sync(0xffffffffu, d1, 1);  d1  += __shfl_xor_sync(0xffffffffu, d1, 2);

    float lossv = 0.f, cntv = 0.f;
    if (tg == 0) {
        int gn0 = rt * 128 + r0loc;
        int gn1 = rt * 128 + r1loc;
        float m0 = g_mask[b * N_ + gn0];
        float m1 = g_mask[b * N_ + gn1];
        float l0 = LN2 * (log2f(rs0) - d0);
        float l1 = LN2 * (log2f(rs1) - d1);
        lossv = l0 * m0 + l1 * m1;
        cntv  = m0 + m1;
    }
#pragma unroll
    for (int off = 16; off; off >>= 1) {
        lossv += __shfl_xor_sync(0xffffffffu, lossv, off);
        cntv  += __shfl_xor_sync(0xffffffffu, cntv, off);
    }
    if (lane == 0) { sred[w] = lossv; sred[8 + w] = cntv; }
    __syncthreads();
    if (tid == 0) {
        float L = 0.f, C = 0.f;
#pragma unroll
        for (int i = 0; i < 8; i++) { L += sred[i]; C += sred[8 + i]; }
        atomicAdd(&g_acc[0], (double)L);
        atomicAdd(&g_acc[1], (double)C);
    }
}

// ---------------- kernel 4: finalize ----------------
__global__ void k_fin(float* out) {
    double t = g_acc[0], nv = g_acc[1];
    out[0] = (nv > 0.0) ? (float)(t / fmax(nv, 1.0)) : 0.f;
}

// ---------------- launch ----------------
extern "C" void kernel_launch(void* const* d_in, const int* in_sizes, int n_in,
                              void* d_out, int out_size) {
    (void)in_sizes; (void)n_in; (void)out_size;
    const float* fa = (const float*)d_in[0];
    const float* fb = (const float*)d_in[1];
    const float* Ha = (const float*)d_in[2];
    const float* Hb = (const float*)d_in[3];
    const float* M  = (const float*)d_in[4];
    float* out = (float*)d_out;

    cudaFuncSetAttribute(k_gemm, cudaFuncAttributeMaxDynamicSharedMemorySize, 98432);

    k_pre<<<dim3(NP, B_, 2), 256>>>(fa, fb, Ha, Hb, M);
    k_gemm<<<dim3(NT, B_), 256, 98432>>>();
    k_fin<<<1, 1>>>(out);
}